// round 14
// baseline (speedup 1.0000x reference)
#include <cuda_runtime.h>
#include <cuda_bf16.h>
#include <stdint.h>

#define N_NODES 100000
#define IN_F 256
#define OUT_F 64

// Scratch: support, CSR row pointers, pre-packed W fragments.
__device__ float g_support[(size_t)N_NODES * OUT_F];
__device__ int   g_row_ptr[N_NODES + 1];
__device__ uint2 g_wfrag_hi[4][1024];
__device__ uint2 g_wfrag_lo[4][1024];

// ===========================================================================
// Common helpers
// ===========================================================================
__device__ __forceinline__ uint32_t smem_u32(const void* p) {
    uint32_t a;
    asm("{ .reg .u64 t; cvta.to.shared.u64 t, %1; cvt.u32.u64 %0, t; }"
        : "=r"(a) : "l"(p));
    return a;
}

#define LDSM_X4(r, addr) \
    asm volatile("ldmatrix.sync.aligned.m8n8.x4.shared.b16 {%0,%1,%2,%3}, [%4];" \
        : "=r"((r)[0]), "=r"((r)[1]), "=r"((r)[2]), "=r"((r)[3]) : "r"(addr))

#define MMA_BF16(d, a, b0, b1) \
    asm volatile("mma.sync.aligned.m16n8k16.row.col.f32.bf16.bf16.f32 " \
        "{%0,%1,%2,%3}, {%4,%5,%6,%7}, {%8,%9}, {%0,%1,%2,%3};" \
        : "+f"((d)[0]), "+f"((d)[1]), "+f"((d)[2]), "+f"((d)[3]) \
        : "r"((a)[0]), "r"((a)[1]), "r"((a)[2]), "r"((a)[3]), "r"(b0), "r"(b1))

// Split pair (x,y) -> packed bf16x2 hi (truncated) + packed bf16x2 lo (rounded).
__device__ __forceinline__ uint32_t split2(float x, float y, uint32_t& lo2) {
    uint32_t bx = __float_as_uint(x), by = __float_as_uint(y), hp;
    asm("prmt.b32 %0, %1, %2, 0x7632;" : "=r"(hp) : "r"(bx), "r"(by));
    float hx = __uint_as_float(bx & 0xFFFF0000u);
    float hy = __uint_as_float(by & 0xFFFF0000u);
    float lx = x - hx, ly = y - hy;
    asm("cvt.rn.bf16x2.f32 %0, %1, %2;" : "=r"(lo2) : "f"(ly), "f"(lx));
    return hp;
}

// ===========================================================================
// FUSED prep: build CSR row_ptr (all threads) + pack W fragments
// (first 4096 global threads). One launch covers both independent tasks.
// ===========================================================================
__global__ __launch_bounds__(256) void prep_kernel(
    const int* __restrict__ rows, int nE, int nRows, int* __restrict__ rp,
    const float* __restrict__ W)
{
    int gid = blockIdx.x * blockDim.x + threadIdx.x;

    if (gid < 4096) {
        int kc = gid >> 10;
        int id = gid & 1023;
        int t = id & 31;
        int j = (id >> 5) & 7;
        int s = id >> 8;
        int k = kc * 64 + s * 16 + (t & 3) * 2;
        int n = j * 8 + (t >> 2);
        float w00 = W[(size_t)k * OUT_F + n];
        float w01 = W[(size_t)(k + 1) * OUT_F + n];
        float w10 = W[(size_t)(k + 8) * OUT_F + n];
        float w11 = W[(size_t)(k + 9) * OUT_F + n];
        uint32_t l0, l1;
        uint32_t h0 = split2(w00, w01, l0);
        uint32_t h1 = split2(w10, w11, l1);
        g_wfrag_hi[kc][id] = make_uint2(h0, h1);
        g_wfrag_lo[kc][id] = make_uint2(l0, l1);
    }

    if (gid < nE) {
        int r = rows[gid];
        int rprev = (gid == 0) ? -1 : rows[gid - 1];
        for (int q = rprev + 1; q <= r; q++) rp[q] = gid;
        if (gid == nE - 1) {
            for (int q = r + 1; q <= nRows; q++) rp[q] = nE;
        }
    }
}

// ===========================================================================
// GEMM + tanh via mma.sync bf16 3-product split — R13 proven (TILE_M=64,
// 4 CTAs/SM). Untouched.
// ===========================================================================
#define TILE_M 64
#define BKC 64
#define A_ROW_BYTES 144
#define A_PART (TILE_M * A_ROW_BYTES)
#define W_PART (4 * 8 * 32 * 8)
#define SM_AHI 0
#define SM_ALO (SM_AHI + A_PART)
#define SM_WHI (SM_ALO + A_PART)
#define SM_WLO (SM_WHI + W_PART)
#define SM_TOTAL_G (SM_WLO + W_PART)

__global__ __launch_bounds__(256, 4) void gemm_mma_kernel(
    const float* __restrict__ A,
    const int* __restrict__ active, float* __restrict__ C, int M)
{
    extern __shared__ char sm[];
    const uint32_t sb = smem_u32(sm);
    const int tid = threadIdx.x;
    const int wid = tid >> 5;
    const int lane = tid & 31;
    const int wm = wid & 3;
    const int wn = wid >> 2;
    const int row0 = blockIdx.x * TILE_M;

    float d[4][4];
    #pragma unroll
    for (int j = 0; j < 4; j++)
        #pragma unroll
        for (int e = 0; e < 4; e++) d[j][e] = 0.f;

    const uint32_t a_lm_base =
        sb + SM_AHI + (uint32_t)(wm * 16 + (lane & 15)) * A_ROW_BYTES
        + (uint32_t)((lane >> 4) * 16);

    #pragma unroll
    for (int kc = 0; kc < 4; kc++) {
        const int kbase = kc * BKC;

        #pragma unroll
        for (int i = 0; i < 4; i++) {
            int idx = tid + i * 256;
            int r = idx >> 4;
            int q = idx & 15;
            int gr = row0 + r;
            float4 v = make_float4(0.f, 0.f, 0.f, 0.f);
            if (gr < M)
                v = *reinterpret_cast<const float4*>(
                    &A[(size_t)gr * IN_F + kbase + (q << 2)]);
            uint32_t l0, l1;
            uint32_t h0 = split2(v.x, v.y, l0);
            uint32_t h1 = split2(v.z, v.w, l1);
            int off = r * A_ROW_BYTES + q * 8;
            *reinterpret_cast<uint2*>(sm + SM_AHI + off) = make_uint2(h0, h1);
            *reinterpret_cast<uint2*>(sm + SM_ALO + off) = make_uint2(l0, l1);
        }

        {
            const uint2* wh = g_wfrag_hi[kc];
            const uint2* wl = g_wfrag_lo[kc];
            uint2* dh = reinterpret_cast<uint2*>(sm + SM_WHI);
            uint2* dl = reinterpret_cast<uint2*>(sm + SM_WLO);
            #pragma unroll
            for (int i = 0; i < 4; i++) {
                int idx = tid + i * 256;
                dh[idx] = wh[idx];
                dl[idx] = wl[idx];
            }
        }
        __syncthreads();

        #pragma unroll
        for (int s = 0; s < 4; s++) {
            uint32_t ah[4], al[4];
            LDSM_X4(ah, a_lm_base + s * 32);
            LDSM_X4(al, a_lm_base + s * 32 + (SM_ALO - SM_AHI));
            const char* whb = sm + SM_WHI + (s * 8 * 32 + wn * 4 * 32 + lane) * 8;
            const char* wlb = sm + SM_WLO + (s * 8 * 32 + wn * 4 * 32 + lane) * 8;
            #pragma unroll
            for (int j = 0; j < 4; j++) {
                uint2 bh = *reinterpret_cast<const uint2*>(whb + j * 256);
                uint2 bl = *reinterpret_cast<const uint2*>(wlb + j * 256);
                MMA_BF16(d[j], ah, bh.x, bh.y);
                MMA_BF16(d[j], al, bh.x, bh.y);
                MMA_BF16(d[j], ah, bl.x, bl.y);
            }
        }
        __syncthreads();
    }

    const int act = *active;
    int rlo = row0 + wm * 16 + (lane >> 2);
    int colb = wn * 32 + (lane & 3) * 2;
    #pragma unroll
    for (int j = 0; j < 4; j++) {
        float2 p0 = make_float2(d[j][0], d[j][1]);
        float2 p1 = make_float2(d[j][2], d[j][3]);
        if (act) {
            p0.x = tanhf(p0.x); p0.y = tanhf(p0.y);
            p1.x = tanhf(p1.x); p1.y = tanhf(p1.y);
        }
        int col = colb + j * 8;
        if (rlo < M)
            *reinterpret_cast<float2*>(&C[(size_t)rlo * OUT_F + col]) = p0;
        if (rlo + 8 < M)
            *reinterpret_cast<float2*>(&C[(size_t)(rlo + 8) * OUT_F + col]) = p1;
    }
}

// ---------------------------------------------------------------------------
// Row-parallel SpMM: each warp handles 4 CONTIGUOUS rows (variance reduction:
// block critical path ~ max over warps of Poisson(64) instead of Poisson(16)).
// Per-row inner body = exact R7 proven loop (half-warp per edge, no shfl
// inside, one float4 store per row). No atomics, no memset.
// ---------------------------------------------------------------------------
#define ROWS_PER_WARP 4

__global__ __launch_bounds__(256) void spmm_row_kernel(
    const int* __restrict__ rp, const int* __restrict__ cols,
    const float* __restrict__ vals, const float* __restrict__ x,
    float* __restrict__ y, int nRows)
{
    const int warp = (blockIdx.x * blockDim.x + threadIdx.x) >> 5;
    const int lane = threadIdx.x & 31;
    const int half = lane >> 4;      // which edge of the pair
    const int fl = (lane & 15) << 2; // feature quad
    const int row0 = warp * ROWS_PER_WARP;
    if (row0 >= nRows) return;

    #pragma unroll
    for (int rr = 0; rr < ROWS_PER_WARP; rr++) {
        const int row = row0 + rr;
        if (row >= nRows) break;

        const int s = rp[row];
        const int e = rp[row + 1];

        float4 acc = make_float4(0.f, 0.f, 0.f, 0.f);
        int b = s + half;
        for (; b + 2 < e; b += 4) {
            int   c0 = __ldg(&cols[b]);
            float v0 = __ldg(&vals[b]);
            int   c1 = __ldg(&cols[b + 2]);
            float v1 = __ldg(&vals[b + 2]);
            float4 x0 = *reinterpret_cast<const float4*>(&x[(size_t)c0 * OUT_F + fl]);
            float4 x1 = *reinterpret_cast<const float4*>(&x[(size_t)c1 * OUT_F + fl]);
            acc.x = fmaf(v0, x0.x, acc.x); acc.y = fmaf(v0, x0.y, acc.y);
            acc.z = fmaf(v0, x0.z, acc.z); acc.w = fmaf(v0, x0.w, acc.w);
            acc.x = fmaf(v1, x1.x, acc.x); acc.y = fmaf(v1, x1.y, acc.y);
            acc.z = fmaf(v1, x1.z, acc.z); acc.w = fmaf(v1, x1.w, acc.w);
        }
        if (b < e) {
            int   c = __ldg(&cols[b]);
            float v = __ldg(&vals[b]);
            float4 xv = *reinterpret_cast<const float4*>(&x[(size_t)c * OUT_F + fl]);
            acc.x = fmaf(v, xv.x, acc.x); acc.y = fmaf(v, xv.y, acc.y);
            acc.z = fmaf(v, xv.z, acc.z); acc.w = fmaf(v, xv.w, acc.w);
        }

        acc.x += __shfl_xor_sync(0xffffffffu, acc.x, 16);
        acc.y += __shfl_xor_sync(0xffffffffu, acc.y, 16);
        acc.z += __shfl_xor_sync(0xffffffffu, acc.z, 16);
        acc.w += __shfl_xor_sync(0xffffffffu, acc.w, 16);

        if (half == 0)
            *reinterpret_cast<float4*>(&y[(size_t)row * OUT_F + fl]) = acc;
    }
}

// ---------------------------------------------------------------------------
extern "C" void kernel_launch(void* const* d_in, const int* in_sizes, int n_in,
                              void* d_out, int out_size)
{
    const float* features = (const float*)d_in[0];   // [N, 256]
    const float* weight   = (const float*)d_in[1];   // [256, 64]
    const int*   adj_rows = (const int*)d_in[2];     // [E] sorted
    const int*   adj_cols = (const int*)d_in[3];     // [E]
    const float* adj_vals = (const float*)d_in[4];   // [E]
    const int*   active   = (const int*)d_in[5];     // scalar

    const int M  = in_sizes[0] / IN_F;               // 100000
    const int nE = in_sizes[2];                      // 1600000

    float* out_first  = (float*)d_out;                          // output [N,64]
    float* out_second = (float*)d_out + (size_t)M * OUT_F;      // az     [N,64]

    float* support = nullptr;
    cudaGetSymbolAddress((void**)&support, g_support);
    int* row_ptr = nullptr;
    cudaGetSymbolAddress((void**)&row_ptr, g_row_ptr);

    cudaFuncSetAttribute(gemm_mma_kernel,
                         cudaFuncAttributeMaxDynamicSharedMemorySize, SM_TOTAL_G);

    // 0) fused prep: CSR row pointers + W fragment packing (one launch)
    prep_kernel<<<(nE + 255) / 256, 256>>>(adj_rows, nE, M, row_ptr, weight);

    // 1) support = tanh(features @ weight)
    int gblocks = (M + TILE_M - 1) / TILE_M;
    gemm_mma_kernel<<<gblocks, 256, SM_TOTAL_G>>>(features, active, support, M);

    // 2) output = adj @ support
    int nwarps = (M + ROWS_PER_WARP - 1) / ROWS_PER_WARP;
    int sblocks = (nwarps + 7) / 8;    // 8 warps per 256-thread block
    spmm_row_kernel<<<sblocks, 256>>>(row_ptr, adj_cols, adj_vals, support, out_first, M);

    // 3) az = adj @ output
    spmm_row_kernel<<<sblocks, 256>>>(row_ptr, adj_cols, adj_vals, out_first, out_second, M);
}

// round 15
// speedup vs baseline: 1.0494x; 1.0494x over previous
#include <cuda_runtime.h>
#include <cuda_fp16.h>
#include <cuda_bf16.h>
#include <stdint.h>

#define N_NODES 100000
#define IN_F 256
#define OUT_F 64

// Scratch: fp16 support + fp16 mirror of output, CSR row ptrs, W fragments.
__device__ __half g_support_h[(size_t)N_NODES * OUT_F];
__device__ __half g_inter_h[(size_t)N_NODES * OUT_F];
__device__ int    g_row_ptr[N_NODES + 1];
__device__ uint2  g_wfrag_hi[4][1024];
__device__ uint2  g_wfrag_lo[4][1024];

// ===========================================================================
// Common helpers
// ===========================================================================
__device__ __forceinline__ uint32_t smem_u32(const void* p) {
    uint32_t a;
    asm("{ .reg .u64 t; cvta.to.shared.u64 t, %1; cvt.u32.u64 %0, t; }"
        : "=r"(a) : "l"(p));
    return a;
}

#define LDSM_X4(r, addr) \
    asm volatile("ldmatrix.sync.aligned.m8n8.x4.shared.b16 {%0,%1,%2,%3}, [%4];" \
        : "=r"((r)[0]), "=r"((r)[1]), "=r"((r)[2]), "=r"((r)[3]) : "r"(addr))

#define MMA_BF16(d, a, b0, b1) \
    asm volatile("mma.sync.aligned.m16n8k16.row.col.f32.bf16.bf16.f32 " \
        "{%0,%1,%2,%3}, {%4,%5,%6,%7}, {%8,%9}, {%0,%1,%2,%3};" \
        : "+f"((d)[0]), "+f"((d)[1]), "+f"((d)[2]), "+f"((d)[3]) \
        : "r"((a)[0]), "r"((a)[1]), "r"((a)[2]), "r"((a)[3]), "r"(b0), "r"(b1))

// Split pair (x,y) -> packed bf16x2 hi (truncated) + packed bf16x2 lo (rounded).
__device__ __forceinline__ uint32_t split2(float x, float y, uint32_t& lo2) {
    uint32_t bx = __float_as_uint(x), by = __float_as_uint(y), hp;
    asm("prmt.b32 %0, %1, %2, 0x7632;" : "=r"(hp) : "r"(bx), "r"(by));
    float hx = __uint_as_float(bx & 0xFFFF0000u);
    float hy = __uint_as_float(by & 0xFFFF0000u);
    float lx = x - hx, ly = y - hy;
    asm("cvt.rn.bf16x2.f32 %0, %1, %2;" : "=r"(lo2) : "f"(ly), "f"(lx));
    return hp;
}

// ===========================================================================
// FUSED prep: build CSR row_ptr (all threads) + pack W fragments
// (first 4096 global threads).
// ===========================================================================
__global__ __launch_bounds__(256) void prep_kernel(
    const int* __restrict__ rows, int nE, int nRows, int* __restrict__ rp,
    const float* __restrict__ W)
{
    int gid = blockIdx.x * blockDim.x + threadIdx.x;

    if (gid < 4096) {
        int kc = gid >> 10;
        int id = gid & 1023;
        int t = id & 31;
        int j = (id >> 5) & 7;
        int s = id >> 8;
        int k = kc * 64 + s * 16 + (t & 3) * 2;
        int n = j * 8 + (t >> 2);
        float w00 = W[(size_t)k * OUT_F + n];
        float w01 = W[(size_t)(k + 1) * OUT_F + n];
        float w10 = W[(size_t)(k + 8) * OUT_F + n];
        float w11 = W[(size_t)(k + 9) * OUT_F + n];
        uint32_t l0, l1;
        uint32_t h0 = split2(w00, w01, l0);
        uint32_t h1 = split2(w10, w11, l1);
        g_wfrag_hi[kc][id] = make_uint2(h0, h1);
        g_wfrag_lo[kc][id] = make_uint2(l0, l1);
    }

    if (gid < nE) {
        int r = rows[gid];
        int rprev = (gid == 0) ? -1 : rows[gid - 1];
        for (int q = rprev + 1; q <= r; q++) rp[q] = gid;
        if (gid == nE - 1) {
            for (int q = r + 1; q <= nRows; q++) rp[q] = nE;
        }
    }
}

// ===========================================================================
// GEMM + tanh via mma.sync bf16 3-product split — R13 structure (TILE_M=64,
// 4 CTAs/SM); epilogue now writes fp16 support directly.
// ===========================================================================
#define TILE_M 64
#define BKC 64
#define A_ROW_BYTES 144
#define A_PART (TILE_M * A_ROW_BYTES)
#define W_PART (4 * 8 * 32 * 8)
#define SM_AHI 0
#define SM_ALO (SM_AHI + A_PART)
#define SM_WHI (SM_ALO + A_PART)
#define SM_WLO (SM_WHI + W_PART)
#define SM_TOTAL_G (SM_WLO + W_PART)

__global__ __launch_bounds__(256, 4) void gemm_mma_kernel(
    const float* __restrict__ A,
    const int* __restrict__ active, __half* __restrict__ C, int M)
{
    extern __shared__ char sm[];
    const uint32_t sb = smem_u32(sm);
    const int tid = threadIdx.x;
    const int wid = tid >> 5;
    const int lane = tid & 31;
    const int wm = wid & 3;
    const int wn = wid >> 2;
    const int row0 = blockIdx.x * TILE_M;

    float d[4][4];
    #pragma unroll
    for (int j = 0; j < 4; j++)
        #pragma unroll
        for (int e = 0; e < 4; e++) d[j][e] = 0.f;

    const uint32_t a_lm_base =
        sb + SM_AHI + (uint32_t)(wm * 16 + (lane & 15)) * A_ROW_BYTES
        + (uint32_t)((lane >> 4) * 16);

    #pragma unroll
    for (int kc = 0; kc < 4; kc++) {
        const int kbase = kc * BKC;

        #pragma unroll
        for (int i = 0; i < 4; i++) {
            int idx = tid + i * 256;
            int r = idx >> 4;
            int q = idx & 15;
            int gr = row0 + r;
            float4 v = make_float4(0.f, 0.f, 0.f, 0.f);
            if (gr < M)
                v = *reinterpret_cast<const float4*>(
                    &A[(size_t)gr * IN_F + kbase + (q << 2)]);
            uint32_t l0, l1;
            uint32_t h0 = split2(v.x, v.y, l0);
            uint32_t h1 = split2(v.z, v.w, l1);
            int off = r * A_ROW_BYTES + q * 8;
            *reinterpret_cast<uint2*>(sm + SM_AHI + off) = make_uint2(h0, h1);
            *reinterpret_cast<uint2*>(sm + SM_ALO + off) = make_uint2(l0, l1);
        }

        {
            const uint2* wh = g_wfrag_hi[kc];
            const uint2* wl = g_wfrag_lo[kc];
            uint2* dh = reinterpret_cast<uint2*>(sm + SM_WHI);
            uint2* dl = reinterpret_cast<uint2*>(sm + SM_WLO);
            #pragma unroll
            for (int i = 0; i < 4; i++) {
                int idx = tid + i * 256;
                dh[idx] = wh[idx];
                dl[idx] = wl[idx];
            }
        }
        __syncthreads();

        #pragma unroll
        for (int s = 0; s < 4; s++) {
            uint32_t ah[4], al[4];
            LDSM_X4(ah, a_lm_base + s * 32);
            LDSM_X4(al, a_lm_base + s * 32 + (SM_ALO - SM_AHI));
            const char* whb = sm + SM_WHI + (s * 8 * 32 + wn * 4 * 32 + lane) * 8;
            const char* wlb = sm + SM_WLO + (s * 8 * 32 + wn * 4 * 32 + lane) * 8;
            #pragma unroll
            for (int j = 0; j < 4; j++) {
                uint2 bh = *reinterpret_cast<const uint2*>(whb + j * 256);
                uint2 bl = *reinterpret_cast<const uint2*>(wlb + j * 256);
                MMA_BF16(d[j], ah, bh.x, bh.y);
                MMA_BF16(d[j], al, bh.x, bh.y);
                MMA_BF16(d[j], ah, bl.x, bl.y);
            }
        }
        __syncthreads();
    }

    // ---- epilogue: tanh + fp16 store ----
    const int act = *active;
    int rlo = row0 + wm * 16 + (lane >> 2);
    int colb = wn * 32 + (lane & 3) * 2;
    #pragma unroll
    for (int j = 0; j < 4; j++) {
        float2 p0 = make_float2(d[j][0], d[j][1]);
        float2 p1 = make_float2(d[j][2], d[j][3]);
        if (act) {
            p0.x = tanhf(p0.x); p0.y = tanhf(p0.y);
            p1.x = tanhf(p1.x); p1.y = tanhf(p1.y);
        }
        int col = colb + j * 8;
        if (rlo < M)
            *reinterpret_cast<__half2*>(&C[(size_t)rlo * OUT_F + col]) =
                __float22half2_rn(p0);
        if (rlo + 8 < M)
            *reinterpret_cast<__half2*>(&C[(size_t)(rlo + 8) * OUT_F + col]) =
                __float22half2_rn(p1);
    }
}

// ---------------------------------------------------------------------------
// Row-parallel SpMM over fp16 input (EXACT R7 schedule, half the bytes):
// one warp per row; half-warp per edge; each lane owns 4 features as
// one 8B uint2 (4 halves). Writes fp32 result + optional fp16 mirror.
// ---------------------------------------------------------------------------
__device__ __forceinline__ void h4_fma(float4& acc, float v, uint2 g) {
    float2 a = __half22float2(*reinterpret_cast<__half2*>(&g.x));
    float2 b = __half22float2(*reinterpret_cast<__half2*>(&g.y));
    acc.x = fmaf(v, a.x, acc.x); acc.y = fmaf(v, a.y, acc.y);
    acc.z = fmaf(v, b.x, acc.z); acc.w = fmaf(v, b.y, acc.w);
}

__global__ __launch_bounds__(256) void spmm_row_kernel(
    const int* __restrict__ rp, const int* __restrict__ cols,
    const float* __restrict__ vals, const __half* __restrict__ x,
    float* __restrict__ y, __half* __restrict__ yh, int write_h, int nRows)
{
    const int row = (blockIdx.x * blockDim.x + threadIdx.x) >> 5;
    if (row >= nRows) return;
    const int lane = threadIdx.x & 31;
    const int half_id = lane >> 4;    // which edge of the pair
    const int fl = (lane & 15) << 2;  // feature quad

    const int s = rp[row];
    const int e = rp[row + 1];

    float4 acc = make_float4(0.f, 0.f, 0.f, 0.f);
    int b = s + half_id;
    for (; b + 2 < e; b += 4) {
        int   c0 = __ldg(&cols[b]);
        float v0 = __ldg(&vals[b]);
        int   c1 = __ldg(&cols[b + 2]);
        float v1 = __ldg(&vals[b + 2]);
        uint2 g0 = *reinterpret_cast<const uint2*>(&x[(size_t)c0 * OUT_F + fl]);
        uint2 g1 = *reinterpret_cast<const uint2*>(&x[(size_t)c1 * OUT_F + fl]);
        h4_fma(acc, v0, g0);
        h4_fma(acc, v1, g1);
    }
    if (b < e) {
        int   c = __ldg(&cols[b]);
        float v = __ldg(&vals[b]);
        uint2 g = *reinterpret_cast<const uint2*>(&x[(size_t)c * OUT_F + fl]);
        h4_fma(acc, v, g);
    }

    acc.x += __shfl_xor_sync(0xffffffffu, acc.x, 16);
    acc.y += __shfl_xor_sync(0xffffffffu, acc.y, 16);
    acc.z += __shfl_xor_sync(0xffffffffu, acc.z, 16);
    acc.w += __shfl_xor_sync(0xffffffffu, acc.w, 16);

    if (half_id == 0) {
        *reinterpret_cast<float4*>(&y[(size_t)row * OUT_F + fl]) = acc;
        if (write_h) {
            __half2 h0 = __float22half2_rn(make_float2(acc.x, acc.y));
            __half2 h1 = __float22half2_rn(make_float2(acc.z, acc.w));
            uint2 hp;
            hp.x = *reinterpret_cast<uint32_t*>(&h0);
            hp.y = *reinterpret_cast<uint32_t*>(&h1);
            *reinterpret_cast<uint2*>(&yh[(size_t)row * OUT_F + fl]) = hp;
        }
    }
}

// ---------------------------------------------------------------------------
extern "C" void kernel_launch(void* const* d_in, const int* in_sizes, int n_in,
                              void* d_out, int out_size)
{
    const float* features = (const float*)d_in[0];   // [N, 256]
    const float* weight   = (const float*)d_in[1];   // [256, 64]
    const int*   adj_rows = (const int*)d_in[2];     // [E] sorted
    const int*   adj_cols = (const int*)d_in[3];     // [E]
    const float* adj_vals = (const float*)d_in[4];   // [E]
    const int*   active   = (const int*)d_in[5];     // scalar

    const int M  = in_sizes[0] / IN_F;               // 100000
    const int nE = in_sizes[2];                      // 1600000

    float* out_first  = (float*)d_out;                          // output [N,64]
    float* out_second = (float*)d_out + (size_t)M * OUT_F;      // az     [N,64]

    __half* support_h = nullptr;
    cudaGetSymbolAddress((void**)&support_h, g_support_h);
    __half* inter_h = nullptr;
    cudaGetSymbolAddress((void**)&inter_h, g_inter_h);
    int* row_ptr = nullptr;
    cudaGetSymbolAddress((void**)&row_ptr, g_row_ptr);

    cudaFuncSetAttribute(gemm_mma_kernel,
                         cudaFuncAttributeMaxDynamicSharedMemorySize, SM_TOTAL_G);

    // 0) fused prep: CSR row pointers + W fragment packing
    prep_kernel<<<(nE + 255) / 256, 256>>>(adj_rows, nE, M, row_ptr, weight);

    // 1) support(fp16) = tanh(features @ weight)
    int gblocks = (M + TILE_M - 1) / TILE_M;
    gemm_mma_kernel<<<gblocks, 256, SM_TOTAL_G>>>(features, active, support_h, M);

    // 2) output = adj @ support  (fp32 to d_out, fp16 mirror to inter_h)
    int sblocks = (M * 32 + 255) / 256;
    spmm_row_kernel<<<sblocks, 256>>>(row_ptr, adj_cols, adj_vals, support_h,
                                      out_first, inter_h, 1, M);

    // 3) az = adj @ output  (gathers fp16 mirror, fp32 result)
    spmm_row_kernel<<<sblocks, 256>>>(row_ptr, adj_cols, adj_vals, inter_h,
                                      out_second, inter_h, 0, M);
}